// round 4
// baseline (speedup 1.0000x reference)
#include <cuda_runtime.h>
#include <cstdint>
#include <math_constants.h>

// Problem constants
#define B_DIM 64
#define S_DIM 2048
#define D_DIM 1024

// Split-K config: 8 warps/CTA, 4 CTAs per batch -> 32 splits per batch
#define WARPS_PER_CTA 8
#define CTAS_PER_B 4
#define SPLITS (WARPS_PER_CTA * CTAS_PER_B)          // 32
#define ROWS_PER_SPLIT (S_DIM / SPLITS)              // 64
#define FLOATS_PER_LANE (D_DIM / 32)                 // 32
#define VEC_PER_LANE (FLOATS_PER_LANE / 4)           // 8

// Scratch for split partials (device globals: allocation-free)
__device__ float g_acc[(size_t)B_DIM * SPLITS * D_DIM];  // 8 MB
__device__ float g_m[B_DIM * SPLITS];
__device__ float g_l[B_DIM * SPLITS];

// ---------------------------------------------------------------------------
// Kernel 1: one-pass online-softmax partial attention per (batch, split)
// Each warp handles ROWS_PER_SPLIT rows of one batch. Masked rows are
// skipped entirely (no enc_out load). acc lives in registers (32 f32/lane).
// NOTE: enc_mask is int32 (harness materializes JAX bool as int32).
// ---------------------------------------------------------------------------
__global__ __launch_bounds__(WARPS_PER_CTA * 32, 2)
void luong_partial_kernel(const int*   __restrict__ enc_mask,
                          const float* __restrict__ enc_out,
                          const float* __restrict__ dec_hid)
{
    const int b    = blockIdx.y;
    const int warp = threadIdx.x >> 5;
    const int lane = threadIdx.x & 31;
    const int split = blockIdx.x * WARPS_PER_CTA + warp;
    const int s0 = split * ROWS_PER_SPLIT;

    // Preload this lane's slice of dec_hid[b,:]  (coalesced float4)
    float h[FLOATS_PER_LANE];
    {
        const float4* hp = reinterpret_cast<const float4*>(dec_hid + (size_t)b * D_DIM);
        #pragma unroll
        for (int i = 0; i < VEC_PER_LANE; i++) {
            float4 v = hp[i * 32 + lane];
            h[i * 4 + 0] = v.x; h[i * 4 + 1] = v.y;
            h[i * 4 + 2] = v.z; h[i * 4 + 3] = v.w;
        }
    }

    float m = -CUDART_INF_F;
    float l = 0.0f;
    float acc[FLOATS_PER_LANE];
    #pragma unroll
    for (int j = 0; j < FLOATS_PER_LANE; j++) acc[j] = 0.0f;

    const int* mask_row = enc_mask + (size_t)b * S_DIM + s0;

    for (int r = 0; r < ROWS_PER_SPLIT; r++) {
        // warp-uniform mask check (broadcast load)
        if (__ldg(mask_row + r)) continue;

        const int s = s0 + r;
        const float4* xr = reinterpret_cast<const float4*>(
            enc_out + ((size_t)b * S_DIM + s) * D_DIM);

        float x[FLOATS_PER_LANE];
        float dsum = 0.0f;
        #pragma unroll
        for (int i = 0; i < VEC_PER_LANE; i++) {
            float4 v = xr[i * 32 + lane];
            x[i * 4 + 0] = v.x; x[i * 4 + 1] = v.y;
            x[i * 4 + 2] = v.z; x[i * 4 + 3] = v.w;
            dsum = fmaf(v.x, h[i * 4 + 0], dsum);
            dsum = fmaf(v.y, h[i * 4 + 1], dsum);
            dsum = fmaf(v.z, h[i * 4 + 2], dsum);
            dsum = fmaf(v.w, h[i * 4 + 3], dsum);
        }
        // warp-wide reduce -> full dot product, broadcast to all lanes
        #pragma unroll
        for (int o = 16; o > 0; o >>= 1)
            dsum += __shfl_xor_sync(0xFFFFFFFFu, dsum, o);

        // online softmax update
        const float m_new = fmaxf(m, dsum);
        const float scale = __expf(m - m_new);   // exp(-inf)=0 on first row
        const float p     = __expf(dsum - m_new);
        l = l * scale + p;
        #pragma unroll
        for (int j = 0; j < FLOATS_PER_LANE; j++)
            acc[j] = fmaf(acc[j], scale, p * x[j]);
        m = m_new;
    }

    // Write partials (coalesced float4 stores)
    const int sidx = b * SPLITS + split;
    float4* ap = reinterpret_cast<float4*>(g_acc + (size_t)sidx * D_DIM);
    #pragma unroll
    for (int i = 0; i < VEC_PER_LANE; i++) {
        float4 v;
        v.x = acc[i * 4 + 0]; v.y = acc[i * 4 + 1];
        v.z = acc[i * 4 + 2]; v.w = acc[i * 4 + 3];
        ap[i * 32 + lane] = v;
    }
    if (lane == 0) {
        g_m[sidx] = m;
        g_l[sidx] = l;
    }
}

// ---------------------------------------------------------------------------
// Kernel 2: merge the SPLITS partials per batch and normalize.
// 64 CTAs x 256 threads; thread t handles float4 slot t of D.
// ---------------------------------------------------------------------------
__global__ __launch_bounds__(256)
void luong_combine_kernel(float* __restrict__ out)
{
    const int b = blockIdx.x;
    const int t = threadIdx.x;   // 0..255, one float4 (4 d-slots) each

    __shared__ float sm[SPLITS];
    __shared__ float sl[SPLITS];
    if (t < SPLITS) {
        sm[t] = g_m[b * SPLITS + t];
        sl[t] = g_l[b * SPLITS + t];
    }
    __syncthreads();

    float mg = -CUDART_INF_F;
    #pragma unroll
    for (int i = 0; i < SPLITS; i++) mg = fmaxf(mg, sm[i]);

    float w[SPLITS];
    float ltot = 0.0f;
    #pragma unroll
    for (int i = 0; i < SPLITS; i++) {
        float wi = (sl[i] > 0.0f) ? __expf(sm[i] - mg) : 0.0f;
        w[i] = wi;
        ltot += sl[i] * wi;
    }
    const float inv = 1.0f / ltot;

    float4 r = make_float4(0.f, 0.f, 0.f, 0.f);
    #pragma unroll 4
    for (int i = 0; i < SPLITS; i++) {
        const float4 a = reinterpret_cast<const float4*>(
            g_acc + ((size_t)b * SPLITS + i) * D_DIM)[t];
        const float wi = w[i];
        r.x = fmaf(a.x, wi, r.x);
        r.y = fmaf(a.y, wi, r.y);
        r.z = fmaf(a.z, wi, r.z);
        r.w = fmaf(a.w, wi, r.w);
    }
    r.x *= inv; r.y *= inv; r.z *= inv; r.w *= inv;
    reinterpret_cast<float4*>(out + (size_t)b * D_DIM)[t] = r;
}

// ---------------------------------------------------------------------------
// Launch.
// Inputs bound by element count (robust to metadata ordering):
//   B*S   = 131072    -> enc_mask (int32; JAX bool materialized as int32)
//   B*S*D = 134217728 -> enc_out  (f32)
//   B*D   = 65536     -> dec_hid  (f32)
// Output: context [B,D] f32.
// ---------------------------------------------------------------------------
extern "C" void kernel_launch(void* const* d_in, const int* in_sizes, int n_in,
                              void* d_out, int out_size)
{
    const int*   enc_mask = nullptr;
    const float* enc_out  = nullptr;
    const float* dec_hid  = nullptr;

    for (int i = 0; i < n_in; i++) {
        if (in_sizes[i] == B_DIM * S_DIM)            enc_mask = (const int*)d_in[i];
        else if (in_sizes[i] == B_DIM * D_DIM)       dec_hid  = (const float*)d_in[i];
        else                                          enc_out  = (const float*)d_in[i];
    }

    float* out = (float*)d_out;

    dim3 grid1(CTAS_PER_B, B_DIM);
    luong_partial_kernel<<<grid1, WARPS_PER_CTA * 32>>>(enc_mask, enc_out, dec_hid);
    luong_combine_kernel<<<B_DIM, 256>>>(out);
}